// round 2
// baseline (speedup 1.0000x reference)
#include <cuda_runtime.h>
#include <cstddef>

// Problem constants (fixed by setup_inputs)
#define B_   2
#define CV   64
#define CR   20
#define E_   64
#define CO   64
#define MV   100000
#define MR   50000
#define NV   262144      // v2p count per batch
#define NN   65536       // bundles per batch (N / bundle, bundle = 4)
#define TOTN (B_ * NN)   // 131072

// ---------------- scratch (device globals: allocation-free) ----------------
__device__ float g_vT[(size_t)B_ * MV * CV];   // v_feat transposed: (B, Mv, 64)
__device__ float g_rT[(size_t)B_ * MR * CR];   // r_feat transposed: (B, Mr, 20)
__device__ float g_qk[(size_t)TOTN * 64];      // qk vectors per bundle
__device__ float g_vb[(size_t)TOTN * 64];      // attention-weighted v per bundle
__device__ float g_outT[(size_t)B_ * MR * CO]; // output transposed: (B, Mr, 64)
__device__ float g_WkqT[CR * 64];              // [c][f] = sum_e Wk[e][f] * Wq[e][c]
__device__ float g_WovT[64 * 64];              // [f][o] = sum_e Wo[o][e] * Wv[e][f]
__device__ int   g_iv[(size_t)B_ * NV];        // flattened v indices (int32)
__device__ int   g_ir[(size_t)TOTN];           // flattened r indices (int32)

// ---------------- index repack: handles int32 OR int64 source ----------------
// If the source is little-endian int64 with values < 2^31 (indices are < 100000),
// every odd 32-bit word is zero. 16 consecutive zero odd-words => int64.
__device__ __forceinline__ bool detect_int64(const int* __restrict__ p) {
    bool i64 = true;
#pragma unroll
    for (int i = 1; i < 32; i += 2) i64 &= (p[i] == 0);
    return i64;
}

__global__ void repack_kernel(const void* __restrict__ v2p,
                              const void* __restrict__ r2p) {
    const int* pv = (const int*)v2p;
    const int* pr = (const int*)r2p;
    bool v64 = detect_int64(pv);
    bool r64 = detect_int64(pr);
    int t = blockIdx.x * blockDim.x + threadIdx.x;
    int stride = gridDim.x * blockDim.x;
    // take ind[:, :, 0] only; pair stride is 2 elements (int32) -> 2 or 4 words
    for (int i = t; i < B_ * NV; i += stride)
        g_iv[i] = v64 ? pv[(size_t)4 * i] : pv[(size_t)2 * i];
    for (int i = t; i < TOTN; i += stride)
        g_ir[i] = r64 ? pr[(size_t)4 * i] : pr[(size_t)2 * i];
}

// ---------------- generic tiled transpose: (B,R,C) -> (B,C,R) ----------------
__global__ void transpose_kernel(const float* __restrict__ in,
                                 float* __restrict__ out, int R, int C) {
    __shared__ float tile[32][33];
    int b = blockIdx.z;
    const float* inb = in + (size_t)b * R * C;
    float* outb = out + (size_t)b * R * C;

    int c = blockIdx.x * 32 + threadIdx.x;
#pragma unroll
    for (int i = threadIdx.y; i < 32; i += 8) {
        int r = blockIdx.y * 32 + i;
        if (r < R && c < C) tile[i][threadIdx.x] = inb[(size_t)r * C + c];
    }
    __syncthreads();
    int r2 = blockIdx.y * 32 + threadIdx.x;
#pragma unroll
    for (int i = threadIdx.y; i < 32; i += 8) {
        int cc = blockIdx.x * 32 + i;
        if (cc < C && r2 < R) outb[(size_t)cc * R + r2] = tile[threadIdx.x][i];
    }
}

// ---------------- fold weights: Wkq = Wk^T Wq,  Wov = Wo Wv ----------------
__global__ void prep_kernel(const float* __restrict__ Wq, const float* __restrict__ Wk,
                            const float* __restrict__ Wv, const float* __restrict__ Wo) {
    int t = blockIdx.x * blockDim.x + threadIdx.x;
    int stride = gridDim.x * blockDim.x;
    for (int i = t; i < CR * 64; i += stride) {
        int c = i / 64, f = i % 64;
        float s = 0.f;
        for (int e = 0; e < 64; e++) s += Wk[e * 64 + f] * Wq[e * CR + c];
        g_WkqT[i] = s;  // layout [c][f]
    }
    for (int i = t; i < 64 * 64; i += stride) {
        int f = i / 64, o = i % 64;
        float s = 0.f;
        for (int e = 0; e < 64; e++) s += Wo[o * 64 + e] * Wv[e * 64 + f];
        g_WovT[i] = s;  // layout [f][o]
    }
}

// ---------------- zero the scatter scratch ----------------
__global__ void zero_kernel(float4* __restrict__ p, int n4) {
    int i = blockIdx.x * blockDim.x + threadIdx.x;
    int stride = gridDim.x * blockDim.x;
    float4 z = make_float4(0.f, 0.f, 0.f, 0.f);
    for (; i < n4; i += stride) p[i] = z;
}

// ---------------- qk kernel: one warp per bundle n ----------------
// qk[n][f] = sum_c Wkq[c][f] * rT[ir(n)][c];  lane holds f=lane and f=lane+32
__global__ __launch_bounds__(256) void qk_kernel() {
    int gw = (blockIdx.x * 256 + threadIdx.x) >> 5;
    int lane = threadIdx.x & 31;

    float wlo[CR], whi[CR];
#pragma unroll
    for (int c = 0; c < CR; c++) {
        wlo[c] = g_WkqT[c * 64 + lane];
        whi[c] = g_WkqT[c * 64 + 32 + lane];
    }

    int n = gw;                       // grid sized exactly: TOTN warps
    int b = n >> 16;

    int ir = g_ir[n];

    float rv = (lane < CR) ? g_rT[((size_t)b * MR + ir) * CR + lane] : 0.f;

    float qlo = 0.f, qhi = 0.f;
#pragma unroll
    for (int c = 0; c < CR; c++) {
        float rc = __shfl_sync(0xffffffffu, rv, c);
        qlo += wlo[c] * rc;
        qhi += whi[c] * rc;
    }
    g_qk[(size_t)n * 64 + lane] = qlo;
    g_qk[(size_t)n * 64 + 32 + lane] = qhi;
}

// ---------------- attention kernel: 8 lanes per bundle, 4 bundles / warp ----------------
__global__ __launch_bounds__(256) void attn_kernel() {
    const unsigned FULL = 0xffffffffu;
    int gw = (blockIdx.x * 256 + threadIdx.x) >> 5;  // warp id, 4 bundles each
    int lane = threadIdx.x & 31;
    int sub = lane >> 3;   // which of the 4 bundles
    int fl = lane & 7;     // feature-lane within bundle (8 floats each)

    int n = gw * 4 + sub;
    int b = n >> 16;

    // lanes 0..15 load the 16 v-indices (4 bundles x 4 members), coalesced
    int iv = 0;
    if (lane < 16) iv = g_iv[(size_t)gw * 16 + lane];

    float4 q0, q1;
    {
        const float4* qp = (const float4*)(g_qk + (size_t)n * 64 + fl * 8);
        q0 = qp[0];
        q1 = qp[1];
    }

    const float* vbase = g_vT + (size_t)b * MV * 64;
    float4 v0[4], v1[4];
    float s[4];
#pragma unroll
    for (int m = 0; m < 4; m++) {
        int ivm = __shfl_sync(FULL, iv, sub * 4 + m);
        const float4* vp = (const float4*)(vbase + (size_t)ivm * 64 + fl * 8);
        v0[m] = vp[0];
        v1[m] = vp[1];
        float p = q0.x * v0[m].x + q0.y * v0[m].y + q0.z * v0[m].z + q0.w * v0[m].w
                + q1.x * v1[m].x + q1.y * v1[m].y + q1.z * v1[m].z + q1.w * v1[m].w;
        p += __shfl_xor_sync(FULL, p, 4);
        p += __shfl_xor_sync(FULL, p, 2);
        p += __shfl_xor_sync(FULL, p, 1);
        s[m] = p * 0.125f;  // 1/sqrt(E=64)
    }

    float mx = fmaxf(fmaxf(s[0], s[1]), fmaxf(s[2], s[3]));
    float e0 = __expf(s[0] - mx), e1 = __expf(s[1] - mx);
    float e2 = __expf(s[2] - mx), e3 = __expf(s[3] - mx);
    float inv = 1.0f / (e0 + e1 + e2 + e3);
    e0 *= inv; e1 *= inv; e2 *= inv; e3 *= inv;

    float4 o0, o1;
    o0.x = e0 * v0[0].x + e1 * v0[1].x + e2 * v0[2].x + e3 * v0[3].x;
    o0.y = e0 * v0[0].y + e1 * v0[1].y + e2 * v0[2].y + e3 * v0[3].y;
    o0.z = e0 * v0[0].z + e1 * v0[1].z + e2 * v0[2].z + e3 * v0[3].z;
    o0.w = e0 * v0[0].w + e1 * v0[1].w + e2 * v0[2].w + e3 * v0[3].w;
    o1.x = e0 * v1[0].x + e1 * v1[1].x + e2 * v1[2].x + e3 * v1[3].x;
    o1.y = e0 * v1[0].y + e1 * v1[1].y + e2 * v1[2].y + e3 * v1[3].y;
    o1.z = e0 * v1[0].z + e1 * v1[1].z + e2 * v1[2].z + e3 * v1[3].z;
    o1.w = e0 * v1[0].w + e1 * v1[1].w + e2 * v1[2].w + e3 * v1[3].w;

    float4* op = (float4*)(g_vb + (size_t)n * 64 + fl * 8);
    op[0] = o0;
    op[1] = o1;
}

// ---------------- output GEMM + scatter: xr = Wov @ vbar, atomicAdd into g_outT ----------------
// block = 256 threads, 128 bundles per block; thread computes 8 outputs x 4 bundles
__global__ __launch_bounds__(256) void out_kernel() {
    __shared__ float sW[64 * 64];     // [f][o]
    __shared__ float sV[128][65];     // [nl][f], padded
    __shared__ int sIr[128];

    int tid = threadIdx.x;
    int ntile = blockIdx.x * 128;

    for (int i = tid; i < 4096; i += 256) sW[i] = g_WovT[i];
    for (int i = tid; i < 2048; i += 256) {
        int nl = i >> 4;
        int f4 = (i & 15) << 2;
        float4 v = *(const float4*)(g_vb + (size_t)(ntile + nl) * 64 + f4);
        sV[nl][f4 + 0] = v.x;
        sV[nl][f4 + 1] = v.y;
        sV[nl][f4 + 2] = v.z;
        sV[nl][f4 + 3] = v.w;
    }
    if (tid < 128) sIr[tid] = g_ir[ntile + tid];
    __syncthreads();

    int og = tid & 7;     // 8 output groups of 8
    int ng = tid >> 3;    // 32 bundle groups of 4
    int o0 = og * 8;
    int nl0 = ng * 4;

    float acc[8][4];
#pragma unroll
    for (int k = 0; k < 8; k++)
#pragma unroll
        for (int j = 0; j < 4; j++) acc[k][j] = 0.f;

#pragma unroll 8
    for (int f = 0; f < 64; f++) {
        float4 w0 = *(const float4*)&sW[f * 64 + o0];
        float4 w1 = *(const float4*)&sW[f * 64 + o0 + 4];
        float va = sV[nl0 + 0][f];
        float vb = sV[nl0 + 1][f];
        float vc = sV[nl0 + 2][f];
        float vd = sV[nl0 + 3][f];
        float w[8] = {w0.x, w0.y, w0.z, w0.w, w1.x, w1.y, w1.z, w1.w};
#pragma unroll
        for (int k = 0; k < 8; k++) {
            acc[k][0] += w[k] * va;
            acc[k][1] += w[k] * vb;
            acc[k][2] += w[k] * vc;
            acc[k][3] += w[k] * vd;
        }
    }

#pragma unroll
    for (int j = 0; j < 4; j++) {
        int nl = nl0 + j;
        int n = ntile + nl;
        int b = n >> 16;
        float* dst = g_outT + ((size_t)b * MR + sIr[nl]) * 64 + o0;
#pragma unroll
        for (int k = 0; k < 8; k++) atomicAdd(dst + k, acc[k][j]);
    }
}

// ---------------- launch ----------------
extern "C" void kernel_launch(void* const* d_in, const int* in_sizes, int n_in,
                              void* d_out, int out_size) {
    const float* v_feat = (const float*)d_in[0];
    const float* r_feat = (const float*)d_in[1];
    const float* Wq = (const float*)d_in[2];
    const float* Wk = (const float*)d_in[3];
    const float* Wv = (const float*)d_in[4];
    const float* Wo = (const float*)d_in[5];
    const void* v2p = d_in[6];
    const void* r2p = d_in[7];
    float* out = (float*)d_out;

    float *vT, *rT, *outT;
    cudaGetSymbolAddress((void**)&vT, g_vT);
    cudaGetSymbolAddress((void**)&rT, g_rT);
    cudaGetSymbolAddress((void**)&outT, g_outT);

    // 0) repack indices to int32 (auto-detects int32 vs int64 source)
    repack_kernel<<<512, 256>>>(v2p, r2p);

    // 1) layout transposes (feature-contiguous gathers)
    transpose_kernel<<<dim3((MV + 31) / 32, (CV + 31) / 32, B_), dim3(32, 8)>>>(v_feat, vT, CV, MV);
    transpose_kernel<<<dim3((MR + 31) / 32, (CR + 31) / 32, B_), dim3(32, 8)>>>(r_feat, rT, CR, MR);

    // 2) fold weights
    prep_kernel<<<8, 256>>>(Wq, Wk, Wv, Wo);

    // 3) zero the scatter scratch
    zero_kernel<<<1024, 256>>>((float4*)outT, (B_ * MR * CO) / 4);

    // 4) qk per bundle
    qk_kernel<<<TOTN / 8, 256>>>();

    // 5) attention (gather v, softmax over 4, weighted sum)
    attn_kernel<<<TOTN / 32, 256>>>();

    // 6) Wov GEMM + scatter-add
    out_kernel<<<TOTN / 128, 256>>>();

    // 7) final transpose (B, Mr, Co) -> (B, Co, Mr)
    transpose_kernel<<<dim3((CO + 31) / 32, (MR + 31) / 32, B_), dim3(32, 8)>>>(outT, out, MR, CO);
}

// round 3
// speedup vs baseline: 1.3406x; 1.3406x over previous
#include <cuda_runtime.h>
#include <cstddef>

// Problem constants (fixed by setup_inputs)
#define B_   2
#define CV   64
#define CR   20
#define E_   64
#define CO   64
#define MV   100000
#define MR   50000
#define NV   262144      // v2p count per batch
#define NN   65536       // bundles per batch (N / bundle, bundle = 4)
#define TOTN (B_ * NN)   // 131072

// ---------------- scratch (device globals: allocation-free) ----------------
__device__ float g_vT[(size_t)B_ * MV * CV];   // v_feat transposed: (B, Mv, 64)
__device__ float g_rT[(size_t)B_ * MR * CR];   // r_feat transposed: (B, Mr, 20)
__device__ float g_vb[(size_t)TOTN * 64];      // attention-weighted v per bundle
__device__ float g_outT[(size_t)B_ * MR * CO]; // output transposed: (B, Mr, 64)
__device__ float g_WkqT[CR * 64];              // [c][f] = sum_e Wk[e][f] * Wq[e][c]
__device__ float g_WovT[64 * 64];              // [f][o] = sum_e Wo[o][e] * Wv[e][f]
__device__ int   g_iv[(size_t)B_ * NV];        // flattened v indices (int32)
__device__ int   g_ir[(size_t)TOTN];           // flattened r indices (int32)

// ---------------- index repack: handles int32 OR int64 source ----------------
__device__ __forceinline__ bool detect_int64(const int* __restrict__ p) {
    bool i64 = true;
#pragma unroll
    for (int i = 1; i < 32; i += 2) i64 &= (p[i] == 0);
    return i64;
}

__global__ void repack_kernel(const void* __restrict__ v2p,
                              const void* __restrict__ r2p) {
    const int* pv = (const int*)v2p;
    const int* pr = (const int*)r2p;
    bool v64 = detect_int64(pv);
    bool r64 = detect_int64(pr);
    int t = blockIdx.x * blockDim.x + threadIdx.x;
    int stride = gridDim.x * blockDim.x;
    for (int i = t; i < B_ * NV; i += stride)
        g_iv[i] = v64 ? pv[(size_t)4 * i] : pv[(size_t)2 * i];
    for (int i = t; i < TOTN; i += stride)
        g_ir[i] = r64 ? pr[(size_t)4 * i] : pr[(size_t)2 * i];
}

// ---------------- generic tiled transpose: (B,R,C) -> (B,C,R) ----------------
__global__ void transpose_kernel(const float* __restrict__ in,
                                 float* __restrict__ out, int R, int C) {
    __shared__ float tile[32][33];
    int b = blockIdx.z;
    const float* inb = in + (size_t)b * R * C;
    float* outb = out + (size_t)b * R * C;

    int c = blockIdx.x * 32 + threadIdx.x;
#pragma unroll
    for (int i = threadIdx.y; i < 32; i += 8) {
        int r = blockIdx.y * 32 + i;
        if (r < R && c < C) tile[i][threadIdx.x] = inb[(size_t)r * C + c];
    }
    __syncthreads();
    int r2 = blockIdx.y * 32 + threadIdx.x;
#pragma unroll
    for (int i = threadIdx.y; i < 32; i += 8) {
        int cc = blockIdx.x * 32 + i;
        if (cc < C && r2 < R) outb[(size_t)cc * R + r2] = tile[threadIdx.x][i];
    }
}

// ---------------- fold weights: one thread per output element ----------------
__global__ void prep_kernel(const float* __restrict__ Wq, const float* __restrict__ Wk,
                            const float* __restrict__ Wv, const float* __restrict__ Wo) {
    int i = blockIdx.x * blockDim.x + threadIdx.x;
    if (i < CR * 64) {
        int c = i >> 6, f = i & 63;
        float s = 0.f;
#pragma unroll
        for (int e = 0; e < 64; e++) s += __ldg(Wk + e * 64 + f) * __ldg(Wq + e * CR + c);
        g_WkqT[i] = s;  // [c][f]
    } else if (i < CR * 64 + 64 * 64) {
        int ii = i - CR * 64;
        int f = ii >> 6, o = ii & 63;
        float s = 0.f;
#pragma unroll
        for (int e = 0; e < 64; e++) s += __ldg(Wo + o * 64 + e) * __ldg(Wv + e * 64 + f);
        g_WovT[ii] = s;  // [f][o]
    }
}

// ---------------- zero the scatter scratch ----------------
__global__ void zero_kernel(float4* __restrict__ p, int n4) {
    int i = blockIdx.x * blockDim.x + threadIdx.x;
    int stride = gridDim.x * blockDim.x;
    float4 z = make_float4(0.f, 0.f, 0.f, 0.f);
    for (; i < n4; i += stride) p[i] = z;
}

// ---------------- fused qk + attention kernel ----------------
// warp = 4 bundles, 8 lanes each. q computed in-warp (no g_qk roundtrip).
__global__ __launch_bounds__(256) void attn_kernel() {
    const unsigned FULL = 0xffffffffu;
    __shared__ float sQ[8][4][64];   // per-warp q staging

    int w = threadIdx.x >> 5;
    int gw = (blockIdx.x * 256 + threadIdx.x) >> 5;  // warp id, 4 bundles each
    int lane = threadIdx.x & 31;
    int sub = lane >> 3;   // which of the 4 bundles
    int fl = lane & 7;     // feature-lane within bundle (8 floats each)

    // ---- q phase: warp computes q for its 4 bundles, lane holds f=lane, lane+32 ----
    {
        float wlo[CR], whi[CR];
#pragma unroll
        for (int c = 0; c < CR; c++) {
            wlo[c] = __ldg(&g_WkqT[c * 64 + lane]);
            whi[c] = __ldg(&g_WkqT[c * 64 + 32 + lane]);
        }
        int irl = 0;
        if (lane < 4) irl = g_ir[gw * 4 + lane];
#pragma unroll
        for (int j = 0; j < 4; j++) {
            int n = gw * 4 + j;
            int b = n >> 16;
            int ir = __shfl_sync(FULL, irl, j);
            float rv = (lane < CR) ? g_rT[((size_t)b * MR + ir) * CR + lane] : 0.f;
            float qlo = 0.f, qhi = 0.f;
#pragma unroll
            for (int c = 0; c < CR; c++) {
                float rc = __shfl_sync(FULL, rv, c);
                qlo += wlo[c] * rc;
                qhi += whi[c] * rc;
            }
            sQ[w][j][lane] = qlo;
            sQ[w][j][lane + 32] = qhi;
        }
    }
    __syncwarp();

    int n = gw * 4 + sub;
    int b = n >> 16;

    // lanes 0..15 load the 16 v-indices (4 bundles x 4 members), coalesced
    int iv = 0;
    if (lane < 16) iv = g_iv[(size_t)gw * 16 + lane];

    float4 q0, q1;
    {
        const float4* qp = (const float4*)&sQ[w][sub][fl * 8];
        q0 = qp[0];
        q1 = qp[1];
    }

    const float* vbase = g_vT + (size_t)b * MV * 64;
    float4 v0[4], v1[4];
    float s[4];
#pragma unroll
    for (int m = 0; m < 4; m++) {
        int ivm = __shfl_sync(FULL, iv, sub * 4 + m);
        const float4* vp = (const float4*)(vbase + (size_t)ivm * 64 + fl * 8);
        v0[m] = vp[0];
        v1[m] = vp[1];
        float p = q0.x * v0[m].x + q0.y * v0[m].y + q0.z * v0[m].z + q0.w * v0[m].w
                + q1.x * v1[m].x + q1.y * v1[m].y + q1.z * v1[m].z + q1.w * v1[m].w;
        p += __shfl_xor_sync(FULL, p, 4);
        p += __shfl_xor_sync(FULL, p, 2);
        p += __shfl_xor_sync(FULL, p, 1);
        s[m] = p * 0.125f;  // 1/sqrt(E=64)
    }

    float mx = fmaxf(fmaxf(s[0], s[1]), fmaxf(s[2], s[3]));
    float e0 = __expf(s[0] - mx), e1 = __expf(s[1] - mx);
    float e2 = __expf(s[2] - mx), e3 = __expf(s[3] - mx);
    float inv = 1.0f / (e0 + e1 + e2 + e3);
    e0 *= inv; e1 *= inv; e2 *= inv; e3 *= inv;

    float4 o0, o1;
    o0.x = e0 * v0[0].x + e1 * v0[1].x + e2 * v0[2].x + e3 * v0[3].x;
    o0.y = e0 * v0[0].y + e1 * v0[1].y + e2 * v0[2].y + e3 * v0[3].y;
    o0.z = e0 * v0[0].z + e1 * v0[1].z + e2 * v0[2].z + e3 * v0[3].z;
    o0.w = e0 * v0[0].w + e1 * v0[1].w + e2 * v0[2].w + e3 * v0[3].w;
    o1.x = e0 * v1[0].x + e1 * v1[1].x + e2 * v1[2].x + e3 * v1[3].x;
    o1.y = e0 * v1[0].y + e1 * v1[1].y + e2 * v1[2].y + e3 * v1[3].y;
    o1.z = e0 * v1[0].z + e1 * v1[1].z + e2 * v1[2].z + e3 * v1[3].z;
    o1.w = e0 * v1[0].w + e1 * v1[1].w + e2 * v1[2].w + e3 * v1[3].w;

    float4* op = (float4*)(g_vb + (size_t)n * 64 + fl * 8);
    op[0] = o0;
    op[1] = o1;
}

// ---------------- output GEMM + scatter: xr = Wov @ vbar, vector RED into g_outT ----------------
__global__ __launch_bounds__(256) void out_kernel() {
    __shared__ float sW[64 * 64];     // [f][o]
    __shared__ float sV[128][65];     // [nl][f], padded
    __shared__ int sIr[128];

    int tid = threadIdx.x;
    int ntile = blockIdx.x * 128;

    for (int i = tid; i < 4096; i += 256) sW[i] = g_WovT[i];
    for (int i = tid; i < 2048; i += 256) {
        int nl = i >> 4;
        int f4 = (i & 15) << 2;
        float4 v = *(const float4*)(g_vb + (size_t)(ntile + nl) * 64 + f4);
        sV[nl][f4 + 0] = v.x;
        sV[nl][f4 + 1] = v.y;
        sV[nl][f4 + 2] = v.z;
        sV[nl][f4 + 3] = v.w;
    }
    if (tid < 128) sIr[tid] = g_ir[ntile + tid];
    __syncthreads();

    int og = tid & 7;     // 8 output groups of 8
    int ng = tid >> 3;    // 32 bundle groups of 4
    int o0 = og * 8;
    int nl0 = ng * 4;

    float acc[8][4];
#pragma unroll
    for (int k = 0; k < 8; k++)
#pragma unroll
        for (int j = 0; j < 4; j++) acc[k][j] = 0.f;

#pragma unroll 8
    for (int f = 0; f < 64; f++) {
        float4 w0 = *(const float4*)&sW[f * 64 + o0];
        float4 w1 = *(const float4*)&sW[f * 64 + o0 + 4];
        float va = sV[nl0 + 0][f];
        float vb = sV[nl0 + 1][f];
        float vc = sV[nl0 + 2][f];
        float vd = sV[nl0 + 3][f];
        float w[8] = {w0.x, w0.y, w0.z, w0.w, w1.x, w1.y, w1.z, w1.w};
#pragma unroll
        for (int k = 0; k < 8; k++) {
            acc[k][0] += w[k] * va;
            acc[k][1] += w[k] * vb;
            acc[k][2] += w[k] * vc;
            acc[k][3] += w[k] * vd;
        }
    }

#pragma unroll
    for (int j = 0; j < 4; j++) {
        int nl = nl0 + j;
        int n = ntile + nl;
        int b = n >> 16;
        float* dst = g_outT + ((size_t)b * MR + sIr[nl]) * 64 + o0;
        asm volatile("red.global.add.v4.f32 [%0], {%1, %2, %3, %4};"
                     :: "l"(dst), "f"(acc[0][j]), "f"(acc[1][j]),
                        "f"(acc[2][j]), "f"(acc[3][j]) : "memory");
        asm volatile("red.global.add.v4.f32 [%0], {%1, %2, %3, %4};"
                     :: "l"(dst + 4), "f"(acc[4][j]), "f"(acc[5][j]),
                        "f"(acc[6][j]), "f"(acc[7][j]) : "memory");
    }
}

// ---------------- launch ----------------
extern "C" void kernel_launch(void* const* d_in, const int* in_sizes, int n_in,
                              void* d_out, int out_size) {
    const float* v_feat = (const float*)d_in[0];
    const float* r_feat = (const float*)d_in[1];
    const float* Wq = (const float*)d_in[2];
    const float* Wk = (const float*)d_in[3];
    const float* Wv = (const float*)d_in[4];
    const float* Wo = (const float*)d_in[5];
    const void* v2p = d_in[6];
    const void* r2p = d_in[7];
    float* out = (float*)d_out;

    float *vT, *rT, *outT;
    cudaGetSymbolAddress((void**)&vT, g_vT);
    cudaGetSymbolAddress((void**)&rT, g_rT);
    cudaGetSymbolAddress((void**)&outT, g_outT);

    // 0) repack indices to int32 (auto-detects int32 vs int64 source)
    repack_kernel<<<512, 256>>>(v2p, r2p);

    // 1) layout transposes (feature-contiguous gathers)
    transpose_kernel<<<dim3((MV + 31) / 32, (CV + 31) / 32, B_), dim3(32, 8)>>>(v_feat, vT, CV, MV);
    transpose_kernel<<<dim3((MR + 31) / 32, (CR + 31) / 32, B_), dim3(32, 8)>>>(r_feat, rT, CR, MR);

    // 2) fold weights (one thread per element)
    prep_kernel<<<(CR * 64 + 64 * 64 + 255) / 256, 256>>>(Wq, Wk, Wv, Wo);

    // 3) zero the scatter scratch
    zero_kernel<<<1024, 256>>>((float4*)outT, (B_ * MR * CO) / 4);

    // 4) fused qk + attention
    attn_kernel<<<TOTN / 32, 256>>>();

    // 5) Wov GEMM + vector-RED scatter
    out_kernel<<<TOTN / 128, 256>>>();

    // 6) final transpose (B, Mr, Co) -> (B, Co, Mr)
    transpose_kernel<<<dim3((CO + 31) / 32, (MR + 31) / 32, B_), dim3(32, 8)>>>(outT, out, MR, CO);
}

// round 4
// speedup vs baseline: 1.3416x; 1.0007x over previous
#include <cuda_runtime.h>
#include <cstddef>

// Problem constants (fixed by setup_inputs)
#define B_   2
#define CV   64
#define CR   20
#define E_   64
#define CO   64
#define MV   100000
#define MR   50000
#define NV   262144      // v2p count per batch
#define NN   65536       // bundles per batch (N / bundle, bundle = 4)
#define TOTN (B_ * NN)   // 131072

// ---------------- scratch (device globals: allocation-free) ----------------
__device__ float g_vT[(size_t)B_ * MV * CV];   // v_feat transposed: (B, Mv, 64)
__device__ float g_rT[(size_t)B_ * MR * CR];   // r_feat transposed: (B, Mr, 20)
__device__ float g_vb[(size_t)TOTN * 64];      // attention-weighted v per bundle
__device__ float g_outT[(size_t)B_ * MR * CO]; // output transposed: (B, Mr, 64)
__device__ float g_WkqT[CR * 64];              // [c][f] = sum_e Wk[e][f] * Wq[e][c]
__device__ float g_WovT[64 * 64];              // [f][o] = sum_e Wo[o][e] * Wv[e][f]
__device__ int   g_iv[(size_t)B_ * NV];        // flattened v indices (int32)
__device__ int   g_ir[(size_t)TOTN];           // flattened r indices (int32)

// ---------------- fused setup kernel: repack + zero + weight-fold ----------------
// blocks [0,512): index repack; [512,768): zero outT; 768: Wkq fold; 769-770: Wov fold
#define SETUP_REPACK_BLKS 512
#define SETUP_ZERO_BLKS   256
#define SETUP_GRID        (SETUP_REPACK_BLKS + SETUP_ZERO_BLKS + 3)

__device__ __forceinline__ bool detect_int64(const int* __restrict__ p) {
    bool i64 = true;
#pragma unroll
    for (int i = 1; i < 32; i += 2) i64 &= (p[i] == 0);
    return i64;
}

__global__ __launch_bounds__(256) void setup_kernel(
    const void* __restrict__ v2p, const void* __restrict__ r2p,
    const float* __restrict__ Wq, const float* __restrict__ Wk,
    const float* __restrict__ Wv, const float* __restrict__ Wo) {
    __shared__ float sA[64 * 64];
    __shared__ float sB[64 * 64];

    int blk = blockIdx.x;
    int tid = threadIdx.x;

    if (blk < SETUP_REPACK_BLKS) {
        // ---- index repack (int32 or int64 source) ----
        const int* pv = (const int*)v2p;
        const int* pr = (const int*)r2p;
        bool v64 = detect_int64(pv);
        bool r64 = detect_int64(pr);
        int t = blk * 256 + tid;
        int stride = SETUP_REPACK_BLKS * 256;
        for (int i = t; i < B_ * NV; i += stride)
            g_iv[i] = v64 ? pv[(size_t)4 * i] : pv[(size_t)2 * i];
        for (int i = t; i < TOTN; i += stride)
            g_ir[i] = r64 ? pr[(size_t)4 * i] : pr[(size_t)2 * i];
    } else if (blk < SETUP_REPACK_BLKS + SETUP_ZERO_BLKS) {
        // ---- zero the scatter scratch ----
        float4* p = (float4*)g_outT;
        int n4 = (B_ * MR * CO) / 4;
        int t = (blk - SETUP_REPACK_BLKS) * 256 + tid;
        int stride = SETUP_ZERO_BLKS * 256;
        float4 z = make_float4(0.f, 0.f, 0.f, 0.f);
        for (int i = t; i < n4; i += stride) p[i] = z;
    } else if (blk == SETUP_REPACK_BLKS + SETUP_ZERO_BLKS) {
        // ---- Wkq fold: sA = Wk (64x64), sB = Wq (64x20) ----
        for (int i = tid; i < 64 * 64; i += 256) sA[i] = Wk[i];
        for (int i = tid; i < 64 * CR; i += 256) sB[i] = Wq[i];
        __syncthreads();
        for (int i = tid; i < CR * 64; i += 256) {
            int c = i >> 6, f = i & 63;
            float s = 0.f;
#pragma unroll
            for (int e = 0; e < 64; e++) s += sA[e * 64 + f] * sB[e * CR + c];
            g_WkqT[i] = s;  // [c][f]
        }
    } else {
        // ---- Wov fold: sA = Wv, sB = Wo; two blocks split the 4096 outputs ----
        int half = blk - (SETUP_REPACK_BLKS + SETUP_ZERO_BLKS + 1);  // 0 or 1
        for (int i = tid; i < 64 * 64; i += 256) sA[i] = Wv[i];
        for (int i = tid; i < 64 * 64; i += 256) sB[i] = Wo[i];
        __syncthreads();
        for (int ii = half * 2048 + tid; ii < half * 2048 + 2048; ii += 256) {
            int f = ii >> 6, o = ii & 63;
            float s = 0.f;
#pragma unroll
            for (int e = 0; e < 64; e++) s += sB[o * 64 + e] * sA[e * 64 + f];
            g_WovT[ii] = s;  // [f][o]
        }
    }
}

// ---------------- generic tiled transpose: (B,R,C) -> (B,C,R) ----------------
__global__ void transpose_kernel(const float* __restrict__ in,
                                 float* __restrict__ out, int R, int C) {
    __shared__ float tile[32][33];
    int b = blockIdx.z;
    const float* inb = in + (size_t)b * R * C;
    float* outb = out + (size_t)b * R * C;

    int c = blockIdx.x * 32 + threadIdx.x;
#pragma unroll
    for (int i = threadIdx.y; i < 32; i += 8) {
        int r = blockIdx.y * 32 + i;
        if (r < R && c < C) tile[i][threadIdx.x] = inb[(size_t)r * C + c];
    }
    __syncthreads();
    int r2 = blockIdx.y * 32 + threadIdx.x;
#pragma unroll
    for (int i = threadIdx.y; i < 32; i += 8) {
        int cc = blockIdx.x * 32 + i;
        if (cc < C && r2 < R) outb[(size_t)cc * R + r2] = tile[threadIdx.x][i];
    }
}

// ---------------- fused qk + attention kernel ----------------
// warp = 4 bundles, 8 lanes each. q computed in-warp (no g_qk roundtrip).
__global__ __launch_bounds__(256) void attn_kernel() {
    const unsigned FULL = 0xffffffffu;
    __shared__ float sQ[8][4][64];   // per-warp q staging

    int w = threadIdx.x >> 5;
    int gw = (blockIdx.x * 256 + threadIdx.x) >> 5;  // warp id, 4 bundles each
    int lane = threadIdx.x & 31;
    int sub = lane >> 3;   // which of the 4 bundles
    int fl = lane & 7;     // feature-lane within bundle (8 floats each)

    // ---- q phase: warp computes q for its 4 bundles, lane holds f=lane, lane+32 ----
    {
        float wlo[CR], whi[CR];
#pragma unroll
        for (int c = 0; c < CR; c++) {
            wlo[c] = __ldg(&g_WkqT[c * 64 + lane]);
            whi[c] = __ldg(&g_WkqT[c * 64 + 32 + lane]);
        }
        int irl = 0;
        if (lane < 4) irl = g_ir[gw * 4 + lane];
#pragma unroll
        for (int j = 0; j < 4; j++) {
            int n = gw * 4 + j;
            int b = n >> 16;
            int ir = __shfl_sync(FULL, irl, j);
            float rv = (lane < CR) ? g_rT[((size_t)b * MR + ir) * CR + lane] : 0.f;
            float qlo = 0.f, qhi = 0.f;
#pragma unroll
            for (int c = 0; c < CR; c++) {
                float rc = __shfl_sync(FULL, rv, c);
                qlo += wlo[c] * rc;
                qhi += whi[c] * rc;
            }
            sQ[w][j][lane] = qlo;
            sQ[w][j][lane + 32] = qhi;
        }
    }
    __syncwarp();

    int n = gw * 4 + sub;
    int b = n >> 16;

    // lanes 0..15 load the 16 v-indices (4 bundles x 4 members), coalesced
    int iv = 0;
    if (lane < 16) iv = g_iv[(size_t)gw * 16 + lane];

    float4 q0, q1;
    {
        const float4* qp = (const float4*)&sQ[w][sub][fl * 8];
        q0 = qp[0];
        q1 = qp[1];
    }

    const float* vbase = g_vT + (size_t)b * MV * 64;
    float4 v0[4], v1[4];
    float s[4];
#pragma unroll
    for (int m = 0; m < 4; m++) {
        int ivm = __shfl_sync(FULL, iv, sub * 4 + m);
        const float4* vp = (const float4*)(vbase + (size_t)ivm * 64 + fl * 8);
        v0[m] = vp[0];
        v1[m] = vp[1];
        float p = q0.x * v0[m].x + q0.y * v0[m].y + q0.z * v0[m].z + q0.w * v0[m].w
                + q1.x * v1[m].x + q1.y * v1[m].y + q1.z * v1[m].z + q1.w * v1[m].w;
        p += __shfl_xor_sync(FULL, p, 4);
        p += __shfl_xor_sync(FULL, p, 2);
        p += __shfl_xor_sync(FULL, p, 1);
        s[m] = p * 0.125f;  // 1/sqrt(E=64)
    }

    float mx = fmaxf(fmaxf(s[0], s[1]), fmaxf(s[2], s[3]));
    float e0 = __expf(s[0] - mx), e1 = __expf(s[1] - mx);
    float e2 = __expf(s[2] - mx), e3 = __expf(s[3] - mx);
    float inv = 1.0f / (e0 + e1 + e2 + e3);
    e0 *= inv; e1 *= inv; e2 *= inv; e3 *= inv;

    float4 o0, o1;
    o0.x = e0 * v0[0].x + e1 * v0[1].x + e2 * v0[2].x + e3 * v0[3].x;
    o0.y = e0 * v0[0].y + e1 * v0[1].y + e2 * v0[2].y + e3 * v0[3].y;
    o0.z = e0 * v0[0].z + e1 * v0[1].z + e2 * v0[2].z + e3 * v0[3].z;
    o0.w = e0 * v0[0].w + e1 * v0[1].w + e2 * v0[2].w + e3 * v0[3].w;
    o1.x = e0 * v1[0].x + e1 * v1[1].x + e2 * v1[2].x + e3 * v1[3].x;
    o1.y = e0 * v1[0].y + e1 * v1[1].y + e2 * v1[2].y + e3 * v1[3].y;
    o1.z = e0 * v1[0].z + e1 * v1[1].z + e2 * v1[2].z + e3 * v1[3].z;
    o1.w = e0 * v1[0].w + e1 * v1[1].w + e2 * v1[2].w + e3 * v1[3].w;

    float4* op = (float4*)(g_vb + (size_t)n * 64 + fl * 8);
    op[0] = o0;
    op[1] = o1;
}

// ---------------- output GEMM (f32x2 packed) + vector-RED scatter ----------------
// block = 256 threads, 128 bundles; thread: 8 outputs (4 f32x2 pairs) x 4 bundles
__global__ __launch_bounds__(256) void out_kernel() {
    __shared__ float sW[64 * 64];     // [f][o]
    __shared__ float sV[128][65];     // [nl][f], padded
    __shared__ int sIr[128];

    int tid = threadIdx.x;
    int ntile = blockIdx.x * 128;

    for (int i = tid; i < 4096; i += 256) sW[i] = g_WovT[i];
    for (int i = tid; i < 2048; i += 256) {
        int nl = i >> 4;
        int f4 = (i & 15) << 2;
        float4 v = *(const float4*)(g_vb + (size_t)(ntile + nl) * 64 + f4);
        sV[nl][f4 + 0] = v.x;
        sV[nl][f4 + 1] = v.y;
        sV[nl][f4 + 2] = v.z;
        sV[nl][f4 + 3] = v.w;
    }
    if (tid < 128) sIr[tid] = g_ir[ntile + tid];
    __syncthreads();

    int og = tid & 7;     // 8 output groups of 8
    int ng = tid >> 3;    // 32 bundle groups of 4
    int o0 = og * 8;
    int nl0 = ng * 4;

    // acc2[p][j]: f32x2 pair of outputs (o0+2p, o0+2p+1) for bundle nl0+j
    unsigned long long acc2[4][4];
#pragma unroll
    for (int p = 0; p < 4; p++)
#pragma unroll
        for (int j = 0; j < 4; j++) acc2[p][j] = 0ull;

#pragma unroll 4
    for (int f = 0; f < 64; f++) {
        float4 w0 = *(const float4*)&sW[f * 64 + o0];
        float4 w1 = *(const float4*)&sW[f * 64 + o0 + 4];
        unsigned long long w2[4];
        asm("mov.b64 %0, {%1, %2};" : "=l"(w2[0]) : "f"(w0.x), "f"(w0.y));
        asm("mov.b64 %0, {%1, %2};" : "=l"(w2[1]) : "f"(w0.z), "f"(w0.w));
        asm("mov.b64 %0, {%1, %2};" : "=l"(w2[2]) : "f"(w1.x), "f"(w1.y));
        asm("mov.b64 %0, {%1, %2};" : "=l"(w2[3]) : "f"(w1.z), "f"(w1.w));
        unsigned long long v2[4];
#pragma unroll
        for (int j = 0; j < 4; j++) {
            float vj = sV[nl0 + j][f];
            asm("mov.b64 %0, {%1, %1};" : "=l"(v2[j]) : "f"(vj));
        }
#pragma unroll
        for (int p = 0; p < 4; p++)
#pragma unroll
            for (int j = 0; j < 4; j++)
                asm("fma.rn.f32x2 %0, %1, %2, %0;"
                    : "+l"(acc2[p][j]) : "l"(w2[p]), "l"(v2[j]));
    }

#pragma unroll
    for (int j = 0; j < 4; j++) {
        int nl = nl0 + j;
        int n = ntile + nl;
        int b = n >> 16;
        float a[8];
#pragma unroll
        for (int p = 0; p < 4; p++)
            asm("mov.b64 {%0, %1}, %2;" : "=f"(a[2 * p]), "=f"(a[2 * p + 1])
                : "l"(acc2[p][j]));
        float* dst = g_outT + ((size_t)b * MR + sIr[nl]) * 64 + o0;
        asm volatile("red.global.add.v4.f32 [%0], {%1, %2, %3, %4};"
                     :: "l"(dst), "f"(a[0]), "f"(a[1]), "f"(a[2]), "f"(a[3]) : "memory");
        asm volatile("red.global.add.v4.f32 [%0], {%1, %2, %3, %4};"
                     :: "l"(dst + 4), "f"(a[4]), "f"(a[5]), "f"(a[6]), "f"(a[7]) : "memory");
    }
}

// ---------------- launch ----------------
extern "C" void kernel_launch(void* const* d_in, const int* in_sizes, int n_in,
                              void* d_out, int out_size) {
    const float* v_feat = (const float*)d_in[0];
    const float* r_feat = (const float*)d_in[1];
    const float* Wq = (const float*)d_in[2];
    const float* Wk = (const float*)d_in[3];
    const float* Wv = (const float*)d_in[4];
    const float* Wo = (const float*)d_in[5];
    const void* v2p = d_in[6];
    const void* r2p = d_in[7];
    float* out = (float*)d_out;

    float *vT, *rT, *outT;
    cudaGetSymbolAddress((void**)&vT, g_vT);
    cudaGetSymbolAddress((void**)&rT, g_rT);
    cudaGetSymbolAddress((void**)&outT, g_outT);

    // 0) fused setup: repack indices + zero scratch + fold weights
    setup_kernel<<<SETUP_GRID, 256>>>(v2p, r2p, Wq, Wk, Wv, Wo);

    // 1) layout transposes (feature-contiguous gathers)
    transpose_kernel<<<dim3((MV + 31) / 32, (CV + 31) / 32, B_), dim3(32, 8)>>>(v_feat, vT, CV, MV);
    transpose_kernel<<<dim3((MR + 31) / 32, (CR + 31) / 32, B_), dim3(32, 8)>>>(r_feat, rT, CR, MR);

    // 2) fused qk + attention
    attn_kernel<<<TOTN / 32, 256>>>();

    // 3) Wov GEMM (f32x2) + vector-RED scatter
    out_kernel<<<TOTN / 128, 256>>>();

    // 4) final transpose (B, Mr, Co) -> (B, Co, Mr)
    transpose_kernel<<<dim3((CO + 31) / 32, (MR + 31) / 32, B_), dim3(32, 8)>>>(outT, out, MR, CO);
}

// round 5
// speedup vs baseline: 1.3889x; 1.0353x over previous
#include <cuda_runtime.h>
#include <cstddef>

// Problem constants (fixed by setup_inputs)
#define B_   2
#define CV   64
#define CR   20
#define E_   64
#define CO   64
#define MV   100000
#define MR   50000
#define NV   262144      // v2p count per batch
#define NN   65536       // bundles per batch (N / bundle, bundle = 4)
#define TOTN (B_ * NN)   // 131072

// ---------------- scratch (device globals: allocation-free) ----------------
__device__ float g_vT[(size_t)B_ * MV * CV];   // v_feat transposed: (B, Mv, 64)
__device__ float g_rT[(size_t)B_ * MR * CR];   // r_feat transposed: (B, Mr, 20)
__device__ float g_vb[(size_t)TOTN * 64];      // attention-weighted v per bundle
__device__ float g_outT[(size_t)B_ * MR * CO]; // output transposed: (B, Mr, 64)
__device__ float g_WkqT[CR * 64];              // [c][f] = sum_e Wk[e][f] * Wq[e][c]
__device__ float g_WovT[64 * 64];              // [f][o] = sum_e Wo[o][e] * Wv[e][f]
__device__ int   g_iv[(size_t)B_ * NV];        // flattened v indices (int32)
__device__ int   g_ir[(size_t)TOTN];           // flattened r indices (int32)

// ---------------- fused setup kernel: repack + zero + weight-fold ----------------
#define SETUP_REPACK_BLKS 512
#define SETUP_ZERO_BLKS   256
#define SETUP_GRID        (SETUP_REPACK_BLKS + SETUP_ZERO_BLKS + 3)

__device__ __forceinline__ bool detect_int64(const int* __restrict__ p) {
    bool i64 = true;
#pragma unroll
    for (int i = 1; i < 32; i += 2) i64 &= (p[i] == 0);
    return i64;
}

__global__ __launch_bounds__(256) void setup_kernel(
    const void* __restrict__ v2p, const void* __restrict__ r2p,
    const float* __restrict__ Wq, const float* __restrict__ Wk,
    const float* __restrict__ Wv, const float* __restrict__ Wo) {
    __shared__ float sA[64 * 64];
    __shared__ float sB[64 * 64];

    int blk = blockIdx.x;
    int tid = threadIdx.x;

    if (blk < SETUP_REPACK_BLKS) {
        const int* pv = (const int*)v2p;
        const int* pr = (const int*)r2p;
        bool v64 = detect_int64(pv);
        bool r64 = detect_int64(pr);
        int t = blk * 256 + tid;
        int stride = SETUP_REPACK_BLKS * 256;
        for (int i = t; i < B_ * NV; i += stride)
            g_iv[i] = v64 ? pv[(size_t)4 * i] : pv[(size_t)2 * i];
        for (int i = t; i < TOTN; i += stride)
            g_ir[i] = r64 ? pr[(size_t)4 * i] : pr[(size_t)2 * i];
    } else if (blk < SETUP_REPACK_BLKS + SETUP_ZERO_BLKS) {
        float4* p = (float4*)g_outT;
        int n4 = (B_ * MR * CO) / 4;
        int t = (blk - SETUP_REPACK_BLKS) * 256 + tid;
        int stride = SETUP_ZERO_BLKS * 256;
        float4 z = make_float4(0.f, 0.f, 0.f, 0.f);
        for (int i = t; i < n4; i += stride) p[i] = z;
    } else if (blk == SETUP_REPACK_BLKS + SETUP_ZERO_BLKS) {
        for (int i = tid; i < 64 * 64; i += 256) sA[i] = Wk[i];
        for (int i = tid; i < 64 * CR; i += 256) sB[i] = Wq[i];
        __syncthreads();
        for (int i = tid; i < CR * 64; i += 256) {
            int c = i >> 6, f = i & 63;
            float s = 0.f;
#pragma unroll
            for (int e = 0; e < 64; e++) s += sA[e * 64 + f] * sB[e * CR + c];
            g_WkqT[i] = s;  // [c][f]
        }
    } else {
        int half = blk - (SETUP_REPACK_BLKS + SETUP_ZERO_BLKS + 1);  // 0 or 1
        for (int i = tid; i < 64 * 64; i += 256) sA[i] = Wv[i];
        for (int i = tid; i < 64 * 64; i += 256) sB[i] = Wo[i];
        __syncthreads();
        for (int ii = half * 2048 + tid; ii < half * 2048 + 2048; ii += 256) {
            int f = ii >> 6, o = ii & 63;
            float s = 0.f;
#pragma unroll
            for (int e = 0; e < 64; e++) s += sB[o * 64 + e] * sA[e * 64 + f];
            g_WovT[ii] = s;  // [f][o]
        }
    }
}

// ---------------- generic tiled transpose: (B,R,C) -> (B,C,R) ----------------
__global__ void transpose_kernel(const float* __restrict__ in,
                                 float* __restrict__ out, int R, int C) {
    __shared__ float tile[32][33];
    int b = blockIdx.z;
    const float* inb = in + (size_t)b * R * C;
    float* outb = out + (size_t)b * R * C;

    int c = blockIdx.x * 32 + threadIdx.x;
#pragma unroll
    for (int i = threadIdx.y; i < 32; i += 8) {
        int r = blockIdx.y * 32 + i;
        if (r < R && c < C) tile[i][threadIdx.x] = inb[(size_t)r * C + c];
    }
    __syncthreads();
    int r2 = blockIdx.y * 32 + threadIdx.x;
#pragma unroll
    for (int i = threadIdx.y; i < 32; i += 8) {
        int cc = blockIdx.x * 32 + i;
        if (cc < C && r2 < R) outb[(size_t)cc * R + r2] = tile[threadIdx.x][i];
    }
}

// ---------------- fused qk + attention kernel ----------------
__global__ __launch_bounds__(256, 6) void attn_kernel() {
    const unsigned FULL = 0xffffffffu;
    __shared__ float sQ[8][4][64];   // per-warp q staging

    int w = threadIdx.x >> 5;
    int gw = (blockIdx.x * 256 + threadIdx.x) >> 5;  // warp id, 4 bundles each
    int lane = threadIdx.x & 31;
    int sub = lane >> 3;   // which of the 4 bundles
    int fl = lane & 7;     // feature-lane within bundle (8 floats each)

    // ---- q phase ----
    {
        float wlo[CR], whi[CR];
#pragma unroll
        for (int c = 0; c < CR; c++) {
            wlo[c] = __ldg(&g_WkqT[c * 64 + lane]);
            whi[c] = __ldg(&g_WkqT[c * 64 + 32 + lane]);
        }
        int irl = 0;
        if (lane < 4) irl = g_ir[gw * 4 + lane];
#pragma unroll
        for (int j = 0; j < 4; j++) {
            int n = gw * 4 + j;
            int b = n >> 16;
            int ir = __shfl_sync(FULL, irl, j);
            float rv = (lane < CR) ? g_rT[((size_t)b * MR + ir) * CR + lane] : 0.f;
            float qlo = 0.f, qhi = 0.f;
#pragma unroll
            for (int c = 0; c < CR; c++) {
                float rc = __shfl_sync(FULL, rv, c);
                qlo += wlo[c] * rc;
                qhi += whi[c] * rc;
            }
            sQ[w][j][lane] = qlo;
            sQ[w][j][lane + 32] = qhi;
        }
    }
    __syncwarp();

    int n = gw * 4 + sub;
    int b = n >> 16;

    int iv = 0;
    if (lane < 16) iv = g_iv[(size_t)gw * 16 + lane];

    float4 q0, q1;
    {
        const float4* qp = (const float4*)&sQ[w][sub][fl * 8];
        q0 = qp[0];
        q1 = qp[1];
    }

    const float* vbase = g_vT + (size_t)b * MV * 64;
    float4 v0[4], v1[4];
    float s[4];
#pragma unroll
    for (int m = 0; m < 4; m++) {
        int ivm = __shfl_sync(FULL, iv, sub * 4 + m);
        const float4* vp = (const float4*)(vbase + (size_t)ivm * 64 + fl * 8);
        v0[m] = vp[0];
        v1[m] = vp[1];
        float p = q0.x * v0[m].x + q0.y * v0[m].y + q0.z * v0[m].z + q0.w * v0[m].w
                + q1.x * v1[m].x + q1.y * v1[m].y + q1.z * v1[m].z + q1.w * v1[m].w;
        p += __shfl_xor_sync(FULL, p, 4);
        p += __shfl_xor_sync(FULL, p, 2);
        p += __shfl_xor_sync(FULL, p, 1);
        s[m] = p * 0.125f;  // 1/sqrt(E=64)
    }

    float mx = fmaxf(fmaxf(s[0], s[1]), fmaxf(s[2], s[3]));
    float e0 = __expf(s[0] - mx), e1 = __expf(s[1] - mx);
    float e2 = __expf(s[2] - mx), e3 = __expf(s[3] - mx);
    float inv = 1.0f / (e0 + e1 + e2 + e3);
    e0 *= inv; e1 *= inv; e2 *= inv; e3 *= inv;

    float4 o0, o1;
    o0.x = e0 * v0[0].x + e1 * v0[1].x + e2 * v0[2].x + e3 * v0[3].x;
    o0.y = e0 * v0[0].y + e1 * v0[1].y + e2 * v0[2].y + e3 * v0[3].y;
    o0.z = e0 * v0[0].z + e1 * v0[1].z + e2 * v0[2].z + e3 * v0[3].z;
    o0.w = e0 * v0[0].w + e1 * v0[1].w + e2 * v0[2].w + e3 * v0[3].w;
    o1.x = e0 * v1[0].x + e1 * v1[1].x + e2 * v1[2].x + e3 * v1[3].x;
    o1.y = e0 * v1[0].y + e1 * v1[1].y + e2 * v1[2].y + e3 * v1[3].y;
    o1.z = e0 * v1[0].z + e1 * v1[1].z + e2 * v1[2].z + e3 * v1[3].z;
    o1.w = e0 * v1[0].w + e1 * v1[1].w + e2 * v1[2].w + e3 * v1[3].w;

    float4* op = (float4*)(g_vb + (size_t)n * 64 + fl * 8);
    op[0] = o0;
    op[1] = o1;
}

// ---------------- output GEMM v2 + vector-RED scatter ----------------
// 256 threads, 256 bundles/block. Thread tile: 8 outputs x 8 bundles (f32x2).
// Shared: sW [64][64] ([f][o]), sVT [64][VPAD] ([f][nl], transposed vb), sIr [256].
#define OUT_TILE 256
#define VPAD 264
#define SMEM_W   0
#define SMEM_VT  (64 * 64)
#define SMEM_IR  (SMEM_VT + 64 * VPAD)
#define OUT_SMEM_FLOATS (SMEM_IR + OUT_TILE)
#define OUT_SMEM_BYTES  (OUT_SMEM_FLOATS * 4)

__global__ __launch_bounds__(256) void out_kernel() {
    extern __shared__ float dsm[];
    float* sW = dsm + SMEM_W;
    float* sVT = dsm + SMEM_VT;
    int* sIr = (int*)(dsm + SMEM_IR);

    int tid = threadIdx.x;
    int ntile = blockIdx.x * OUT_TILE;

    // load Wov [f][o]
    {
        float4* d4 = (float4*)sW;
        const float4* s4 = (const float4*)g_WovT;
        for (int i = tid; i < 64 * 64 / 4; i += 256) d4[i] = s4[i];
    }
    // load vb for 256 bundles, store transposed sVT[f][nl]
    {
        int nl = tid;
        const float4* src = (const float4*)(g_vb + (size_t)(ntile + nl) * 64);
#pragma unroll
        for (int c = 0; c < 16; c++) {
            float4 v = src[c];
            int f = c * 4;
            sVT[(f + 0) * VPAD + nl] = v.x;
            sVT[(f + 1) * VPAD + nl] = v.y;
            sVT[(f + 2) * VPAD + nl] = v.z;
            sVT[(f + 3) * VPAD + nl] = v.w;
        }
        sIr[nl] = g_ir[ntile + nl];
    }
    __syncthreads();

    int og = tid & 7;     // 8 output groups of 8 (broadcast-friendly W reads)
    int ng = tid >> 3;    // 32 bundle groups of 8
    int o0 = og * 8;
    int nl0 = ng * 8;

    // acc2[p][j]: outputs (o0+2p, o0+2p+1) for bundle nl0+j
    unsigned long long acc2[4][8];
#pragma unroll
    for (int p = 0; p < 4; p++)
#pragma unroll
        for (int j = 0; j < 8; j++) acc2[p][j] = 0ull;

#pragma unroll 4
    for (int f = 0; f < 64; f++) {
        const float* wrow = sW + f * 64 + o0;
        float4 w0 = *(const float4*)wrow;
        float4 w1 = *(const float4*)(wrow + 4);
        unsigned long long w2[4];
        asm("mov.b64 %0, {%1, %2};" : "=l"(w2[0]) : "f"(w0.x), "f"(w0.y));
        asm("mov.b64 %0, {%1, %2};" : "=l"(w2[1]) : "f"(w0.z), "f"(w0.w));
        asm("mov.b64 %0, {%1, %2};" : "=l"(w2[2]) : "f"(w1.x), "f"(w1.y));
        asm("mov.b64 %0, {%1, %2};" : "=l"(w2[3]) : "f"(w1.z), "f"(w1.w));

        const float* vrow = sVT + f * VPAD + nl0;
        float4 va = *(const float4*)vrow;
        float4 vb4 = *(const float4*)(vrow + 4);
        unsigned long long v2[8];
        asm("mov.b64 %0, {%1, %1};" : "=l"(v2[0]) : "f"(va.x));
        asm("mov.b64 %0, {%1, %1};" : "=l"(v2[1]) : "f"(va.y));
        asm("mov.b64 %0, {%1, %1};" : "=l"(v2[2]) : "f"(va.z));
        asm("mov.b64 %0, {%1, %1};" : "=l"(v2[3]) : "f"(va.w));
        asm("mov.b64 %0, {%1, %1};" : "=l"(v2[4]) : "f"(vb4.x));
        asm("mov.b64 %0, {%1, %1};" : "=l"(v2[5]) : "f"(vb4.y));
        asm("mov.b64 %0, {%1, %1};" : "=l"(v2[6]) : "f"(vb4.z));
        asm("mov.b64 %0, {%1, %1};" : "=l"(v2[7]) : "f"(vb4.w));

#pragma unroll
        for (int p = 0; p < 4; p++)
#pragma unroll
            for (int j = 0; j < 8; j++)
                asm("fma.rn.f32x2 %0, %1, %2, %0;"
                    : "+l"(acc2[p][j]) : "l"(w2[p]), "l"(v2[j]));
    }

#pragma unroll
    for (int j = 0; j < 8; j++) {
        int nl = nl0 + j;
        int n = ntile + nl;
        int b = n >> 16;
        float a[8];
#pragma unroll
        for (int p = 0; p < 4; p++)
            asm("mov.b64 {%0, %1}, %2;" : "=f"(a[2 * p]), "=f"(a[2 * p + 1])
                : "l"(acc2[p][j]));
        float* dst = g_outT + ((size_t)b * MR + sIr[nl]) * 64 + o0;
        asm volatile("red.global.add.v4.f32 [%0], {%1, %2, %3, %4};"
                     :: "l"(dst), "f"(a[0]), "f"(a[1]), "f"(a[2]), "f"(a[3]) : "memory");
        asm volatile("red.global.add.v4.f32 [%0], {%1, %2, %3, %4};"
                     :: "l"(dst + 4), "f"(a[4]), "f"(a[5]), "f"(a[6]), "f"(a[7]) : "memory");
    }
}

// ---------------- launch ----------------
extern "C" void kernel_launch(void* const* d_in, const int* in_sizes, int n_in,
                              void* d_out, int out_size) {
    const float* v_feat = (const float*)d_in[0];
    const float* r_feat = (const float*)d_in[1];
    const float* Wq = (const float*)d_in[2];
    const float* Wk = (const float*)d_in[3];
    const float* Wv = (const float*)d_in[4];
    const float* Wo = (const float*)d_in[5];
    const void* v2p = d_in[6];
    const void* r2p = d_in[7];
    float* out = (float*)d_out;

    float *vT, *rT, *outT;
    cudaGetSymbolAddress((void**)&vT, g_vT);
    cudaGetSymbolAddress((void**)&rT, g_rT);
    cudaGetSymbolAddress((void**)&outT, g_outT);

    static bool attr_done = false;
    if (!attr_done) {
        cudaFuncSetAttribute(out_kernel, cudaFuncAttributeMaxDynamicSharedMemorySize,
                             OUT_SMEM_BYTES);
        attr_done = true;
    }

    // 0) fused setup: repack indices + zero scratch + fold weights
    setup_kernel<<<SETUP_GRID, 256>>>(v2p, r2p, Wq, Wk, Wv, Wo);

    // 1) layout transposes (feature-contiguous gathers)
    transpose_kernel<<<dim3((MV + 31) / 32, (CV + 31) / 32, B_), dim3(32, 8)>>>(v_feat, vT, CV, MV);
    transpose_kernel<<<dim3((MR + 31) / 32, (CR + 31) / 32, B_), dim3(32, 8)>>>(r_feat, rT, CR, MR);

    // 2) fused qk + attention
    attn_kernel<<<TOTN / 32, 256>>>();

    // 3) Wov GEMM v2 (8x8 f32x2 tile) + vector-RED scatter
    out_kernel<<<TOTN / OUT_TILE, 256, OUT_SMEM_BYTES>>>();

    // 4) final transpose (B, Mr, Co) -> (B, Co, Mr)
    transpose_kernel<<<dim3((CO + 31) / 32, (MR + 31) / 32, B_), dim3(32, 8)>>>(outT, out, MR, CO);
}